// round 9
// baseline (speedup 1.0000x reference)
#include <cuda_runtime.h>
#include <cuda_bf16.h>
#include <cstddef>

// Problem constants
#define SS   48      // sequence length
#define NBLK 128     // persistent grid size (<= 148 SMs -> all co-resident)
#define EPSL 1e-5f

// ---------------- device scratch (allocation-free rule: __device__ globals) ---
__device__ float g_g0[2 * SS * 64 * 2048];   // LN(x @ W_ih0^T): row = d*3072+s*64+b
__device__ float g_g1[2 * 64 * 2048];        // LN(xc @ W_ih1^T): row = d*64+b
__device__ float g_pre[2 * 64 * 2048];       // per-step h @ W_hh^T
__device__ float g_h[2 * 64 * 512];          // hidden state [d][b][k]
__device__ float g_xc[64 * 1024];            // concat(hf, hb) [b][1024]
__device__ float g_wt[2 * 512 * 2048];       // W_hh transposed: [d][k][g]
__device__ unsigned g_cnt;                   // grid-barrier arrival counter

// ---------------- packed fp32x2 helpers ----------------
typedef unsigned long long u64t;

__device__ __forceinline__ void ffma2(u64t& d, u64t a, u64t b) {
    asm("fma.rn.f32x2 %0, %1, %2, %0;" : "+l"(d) : "l"(a), "l"(b));
}
__device__ __forceinline__ u64t dup2(float x) {
    u64t r; asm("mov.b64 %0, {%1, %1};" : "=l"(r) : "f"(x)); return r;
}
__device__ __forceinline__ float2 unpk(u64t v) {
    float2 r; asm("mov.b64 {%0, %1}, %2;" : "=f"(r.x), "=f"(r.y) : "l"(v)); return r;
}

__device__ __forceinline__ float sigf(float x) { return 1.f / (1.f + __expf(-x)); }

// block-wide (256 threads, 8 warps) sum; returns total to all threads
__device__ __forceinline__ float blk_sum(float x, float* sred) {
#pragma unroll
    for (int o = 16; o > 0; o >>= 1) x += __shfl_down_sync(0xffffffffu, x, o);
    const int w = threadIdx.x >> 5;
    if ((threadIdx.x & 31) == 0) sred[w] = x;
    __syncthreads();
    float t = 0.f;
#pragma unroll
    for (int i = 0; i < 8; ++i) t += sred[i];
    __syncthreads();
    return t;
}

// grid-wide barrier over exactly NBLK resident CTAs (monotonic counter).
__device__ __forceinline__ void gbar(int* nbar) {
    __syncthreads();
    if (threadIdx.x == 0) {
        ++(*nbar);
        const unsigned tgt = (unsigned)(*nbar) * NBLK;
        __threadfence();
        atomicAdd(&g_cnt, 1u);
        while (*(volatile unsigned*)&g_cnt < tgt) __nanosleep(32);
        __threadfence();
    }
    __syncthreads();
}

// ---------------- K0: init hidden state + barrier counter ----------------
__global__ void k_init() {
    const int i = blockIdx.x * 256 + threadIdx.x;
    if (i < 2 * 64 * 512) g_h[i] = 0.f;
    if (i == 0) g_cnt = 0u;
}

// ---------------- KT: transpose W_hh [d][g][k] -> g_wt [d][k][g] -------------
__global__ __launch_bounds__(256) void k_prep_wt(const float* __restrict__ w) {
    __shared__ float t[32][33];
    const int d  = blockIdx.z;
    const int g0 = blockIdx.x * 32;
    const int k0 = blockIdx.y * 32;
    const int x  = threadIdx.x;   // 0..31
    const int y  = threadIdx.y;   // 0..7
#pragma unroll
    for (int i = 0; i < 32; i += 8)
        t[y + i][x] = w[((size_t)(d * 2048 + g0 + y + i)) * 512 + k0 + x];
    __syncthreads();
#pragma unroll
    for (int i = 0; i < 32; i += 8)
        g_wt[((size_t)(d * 512 + k0 + y + i)) * 2048 + g0 + x] = t[x][y + i];
}

// ---------------- K1: input GEMM  g0raw[row][g] = x[b][s][:] . w_ih0[d][g][:]
// row = d*3072 + s*64 + b.  M=6144, N=2048, K=512. 128x128 tiles, FFMA2 micro.
__global__ __launch_bounds__(256) void k_gemm_ih0(const float* __restrict__ x,
                                                  const float* __restrict__ w) {
    __shared__ float Asm[16 * 132];   // [k][m]
    __shared__ float Wsm[16 * 132];   // [k][n]
    const int tid   = threadIdx.x;
    const int tcol  = tid & 15;
    const int trow  = tid >> 4;
    const int mbase = blockIdx.y * 128;
    const int nbase = blockIdx.x * 128;
    const int d     = mbase / 3072;   // tile never straddles a direction

    u64t acc[4][8];
#pragma unroll
    for (int i = 0; i < 4; ++i)
#pragma unroll
        for (int j = 0; j < 8; ++j) acc[i][j] = 0ull;

    for (int k0 = 0; k0 < 512; k0 += 16) {
        __syncthreads();
#pragma unroll
        for (int it = 0; it < 2; ++it) {
            const int idx = tid + 256 * it;
            const int m   = idx >> 2;
            const int kq  = (idx & 3) * 4;
            const int rem = (mbase + m) % 3072;
            const int s   = rem >> 6;
            const int b   = rem & 63;
            float4 va = *(const float4*)(x + ((size_t)(b * 48 + s)) * 512 + k0 + kq);
            Asm[(kq + 0) * 132 + m] = va.x;
            Asm[(kq + 1) * 132 + m] = va.y;
            Asm[(kq + 2) * 132 + m] = va.z;
            Asm[(kq + 3) * 132 + m] = va.w;
            float4 vw = *(const float4*)(w + ((size_t)(d * 2048 + nbase + m)) * 512 + k0 + kq);
            Wsm[(kq + 0) * 132 + m] = vw.x;
            Wsm[(kq + 1) * 132 + m] = vw.y;
            Wsm[(kq + 2) * 132 + m] = vw.z;
            Wsm[(kq + 3) * 132 + m] = vw.w;
        }
        __syncthreads();
#pragma unroll
        for (int kk = 0; kk < 16; ++kk) {
            // a: 8 m-values as 4 packed pairs (ulonglong2 loads, 16B aligned: 132*4=528)
            ulonglong2 ua0 = *(const ulonglong2*)&Asm[kk * 132 + trow * 4];
            ulonglong2 ua1 = *(const ulonglong2*)&Asm[kk * 132 + 64 + trow * 4];
            const u64t up[4] = {ua0.x, ua0.y, ua1.x, ua1.y};
            // b: 8 n-values, duplicated
            float4 b0 = *(const float4*)&Wsm[kk * 132 + tcol * 4];
            float4 b1 = *(const float4*)&Wsm[kk * 132 + 64 + tcol * 4];
            const u64t db[8] = {dup2(b0.x), dup2(b0.y), dup2(b0.z), dup2(b0.w),
                                dup2(b1.x), dup2(b1.y), dup2(b1.z), dup2(b1.w)};
#pragma unroll
            for (int p = 0; p < 4; ++p)
#pragma unroll
                for (int j = 0; j < 8; ++j) ffma2(acc[p][j], up[p], db[j]);
        }
    }
    // epilogue: pair p covers rows m_lo/m_hi
#pragma unroll
    for (int p = 0; p < 4; ++p) {
        const int m_lo = (p < 2) ? (trow * 4 + 2 * p) : (64 + trow * 4 + 2 * (p - 2));
        float2 u[8];
#pragma unroll
        for (int j = 0; j < 8; ++j) u[j] = unpk(acc[p][j]);
        const size_t rlo = (size_t)(mbase + m_lo) * 2048 + nbase;
        const size_t rhi = rlo + 2048;
        *(float4*)(g_g0 + rlo + tcol * 4)      = make_float4(u[0].x, u[1].x, u[2].x, u[3].x);
        *(float4*)(g_g0 + rlo + 64 + tcol * 4) = make_float4(u[4].x, u[5].x, u[6].x, u[7].x);
        *(float4*)(g_g0 + rhi + tcol * 4)      = make_float4(u[0].y, u[1].y, u[2].y, u[3].y);
        *(float4*)(g_g0 + rhi + 64 + tcol * 4) = make_float4(u[4].y, u[5].y, u[6].y, u[7].y);
    }
}

// ---------------- K2: in-place row LayerNorm over width 2048 -----------------
__global__ __launch_bounds__(256) void k_ln_rows(int which,
                                                 const float* __restrict__ gam,
                                                 const float* __restrict__ bet,
                                                 int rows_per_dir) {
    __shared__ float sred[8];
    float* p = which ? g_g1 : g_g0;
    const int row = blockIdx.x;
    const int d   = row / rows_per_dir;
    const size_t base = (size_t)row * 2048;
    float v[8];
#pragma unroll
    for (int r = 0; r < 8; ++r) v[r] = p[base + threadIdx.x + 256 * r];
    float s = 0.f;
#pragma unroll
    for (int r = 0; r < 8; ++r) s += v[r];
    const float mu = blk_sum(s, sred) * (1.f / 2048.f);
    float sq = 0.f;
#pragma unroll
    for (int r = 0; r < 8; ++r) { const float t = v[r] - mu; sq += t * t; }
    const float var = blk_sum(sq, sred) * (1.f / 2048.f);
    const float rs  = rsqrtf(var + EPSL);
#pragma unroll
    for (int r = 0; r < 8; ++r) {
        const int idx = threadIdx.x + 256 * r;
        p[base + idx] = (v[r] - mu) * rs * gam[d * 2048 + idx] + bet[d * 2048 + idx];
    }
}

// ---------------- K3: xc GEMM  g1raw[d][b][g] = xc[b][:1024] . w_ih1[d][g][:]
__global__ __launch_bounds__(256) void k_gemm_xc(const float* __restrict__ w) {
    __shared__ float As[64 * 68];
    __shared__ float Ws[32 * 68];
    const int tid = threadIdx.x;
    const int j   = blockIdx.x;
    const int d   = j & 1;
    const int gB  = (j >> 1) * 32;
    const int tx  = tid & 31, ty = tid >> 5;
    float acc[8] = {0.f, 0.f, 0.f, 0.f, 0.f, 0.f, 0.f, 0.f};
    const float* wbase = w + ((size_t)(d * 2048 + gB)) * 1024;
    for (int k0 = 0; k0 < 1024; k0 += 64) {
        __syncthreads();
#pragma unroll
        for (int it = 0; it < 4; ++it) {
            const int idx = tid + 256 * it;
            const int b   = idx >> 4;
            const int kq  = (idx & 15) * 4;
            *(float4*)&As[b * 68 + kq] = *(const float4*)(g_xc + (size_t)b * 1024 + k0 + kq);
        }
#pragma unroll
        for (int it = 0; it < 2; ++it) {
            const int idx = tid + 256 * it;
            const int gg  = idx >> 4;
            const int kq  = (idx & 15) * 4;
            *(float4*)&Ws[gg * 68 + kq] = *(const float4*)(wbase + (size_t)gg * 1024 + k0 + kq);
        }
        __syncthreads();
#pragma unroll
        for (int kk = 0; kk < 64; kk += 4) {
            float4 wv = *(const float4*)&Ws[tx * 68 + kk];
#pragma unroll
            for (int i = 0; i < 8; ++i) {
                float4 av = *(const float4*)&As[(ty * 8 + i) * 68 + kk];
                acc[i] = fmaf(av.x, wv.x, acc[i]);
                acc[i] = fmaf(av.y, wv.y, acc[i]);
                acc[i] = fmaf(av.z, wv.z, acc[i]);
                acc[i] = fmaf(av.w, wv.w, acc[i]);
            }
        }
    }
#pragma unroll
    for (int i = 0; i < 8; ++i)
        g_g1[((size_t)d * 64 + ty * 8 + i) * 2048 + gB + tx] = acc[i];
}

// ---------------- K4: persistent recurrence kernel ----------------
// Phase A (per CTA: dir dA, 32-g slice gB): pre = h @ W_hh^T using broadcast
// micro-kernel: warp = 32 b-rows (one per lane) x 8 g-cols; FFMA2 g-pairs.
// Phase B (per CTA: dir dB, batch bB): LN + gates + cell + output LN.
__global__ __launch_bounds__(256, 1) void k_recur(int per_step,
                                                  const float* __restrict__ lnh_g,
                                                  const float* __restrict__ lnh_b,
                                                  const float* __restrict__ lno_g,
                                                  const float* __restrict__ lno_b,
                                                  float* outp) {
    __shared__ u64t  Asd[64 * 65];   // [b][k] duplicated h values (33,280 B)
    __shared__ float Wsf[64 * 36];   // [k][g] transposed W slice      (9,216 B)
    __shared__ float sred[8];

    const int tid = threadIdx.x;
    const int j   = blockIdx.x;
    // phase-A identity
    const int dA   = j & 1;
    const int gB   = (j >> 1) * 32;
    const int lane = tid & 31;
    const int wrp  = tid >> 5;                 // 0..7
    const int bb   = (wrp & 1) * 32 + lane;    // owned b row
    const int gof  = (wrp >> 1) * 8;           // owned g offset within 32
    // phase-B identity
    const int dB = j >> 6;
    const int bB = j & 63;

    const float* gin = per_step ? g_g0 : g_g1;
    float* op = outp ? outp : g_xc;
    const float* wt = g_wt + (size_t)dA * 512 * 2048 + gB;

    float c0 = 0.f, c1 = 0.f;
    int nbar = 0;

    for (int step = 0; step < SS; ++step) {
        // ---- phase A ----
        u64t acc0 = 0ull, acc1 = 0ull, acc2 = 0ull, acc3 = 0ull;
        for (int k0 = 0; k0 < 512; k0 += 64) {
            __syncthreads();
            // stage h (duplicated) : 64 b x 64 k
#pragma unroll
            for (int it = 0; it < 16; ++it) {
                const int idx = tid + 256 * it;
                const int b   = idx >> 6;
                const int kk  = idx & 63;
                const float v = __ldcg(g_h + ((size_t)dA * 64 + b) * 512 + k0 + kk);
                Asd[b * 65 + kk] = dup2(v);
            }
            // stage W slice: [k][g] 64 x 32 (coalesced from pre-transposed g_wt)
#pragma unroll
            for (int it = 0; it < 2; ++it) {
                const int idx = tid + 256 * it;
                const int k   = idx >> 3;
                const int gq  = (idx & 7) * 4;
                *(float4*)&Wsf[k * 36 + gq] =
                    *(const float4*)(wt + ((size_t)(k0 + k)) * 2048 + gq);
            }
            __syncthreads();
#pragma unroll 8
            for (int kk = 0; kk < 64; ++kk) {
                const u64t a = Asd[bb * 65 + kk];                       // LDS.64, conflict-free
                ulonglong2 w01 = *(const ulonglong2*)&Wsf[kk * 36 + gof];     // broadcast
                ulonglong2 w23 = *(const ulonglong2*)&Wsf[kk * 36 + gof + 4]; // broadcast
                ffma2(acc0, a, w01.x);
                ffma2(acc1, a, w01.y);
                ffma2(acc2, a, w23.x);
                ffma2(acc3, a, w23.y);
            }
        }
        {
            const float2 a0 = unpk(acc0), a1 = unpk(acc1), a2 = unpk(acc2), a3 = unpk(acc3);
            float* pr = g_pre + ((size_t)dA * 64 + bb) * 2048 + gB + gof;
            __stcg((float4*)pr,       make_float4(a0.x, a0.y, a1.x, a1.y));
            __stcg((float4*)(pr + 4), make_float4(a2.x, a2.y, a3.x, a3.y));
        }

        gbar(&nbar);   // pre ready

        // ---- phase B: gates, cell, output-LN for row (dB, bB)
        float v[8];
        const float* prow = g_pre + ((size_t)dB * 64 + bB) * 2048;
#pragma unroll
        for (int r = 0; r < 8; ++r) v[r] = __ldcg(prow + tid + 256 * r);

        float s = 0.f;
#pragma unroll
        for (int r = 0; r < 8; ++r) s += v[r];
        const float mu = blk_sum(s, sred) * (1.f / 2048.f);
        float sq = 0.f;
#pragma unroll
        for (int r = 0; r < 8; ++r) { const float t = v[r] - mu; sq += t * t; }
        const float var = blk_sum(sq, sred) * (1.f / 2048.f);
        const float rs  = rsqrtf(var + EPSL);

        const int s_eff = per_step ? ((dB == 0) ? step : (SS - 1 - step)) : 0;
        const float* grow = per_step
            ? gin + (((size_t)dB * SS + s_eff) * 64 + bB) * 2048
            : gin + ((size_t)dB * 64 + bB) * 2048;

        float gate[8];
#pragma unroll
        for (int r = 0; r < 8; ++r) {
            const int idx = tid + 256 * r;
            gate[r] = grow[idx] + ((v[r] - mu) * rs * lnh_g[dB * 2048 + idx] + lnh_b[dB * 2048 + idx]);
        }
        const float i0 = sigf(gate[0]), i1 = sigf(gate[1]);
        const float f0 = sigf(gate[2]), f1 = sigf(gate[3]);
        const float o0 = sigf(gate[4]), o1 = sigf(gate[5]);
        const float q0 = tanhf(gate[6]), q1 = tanhf(gate[7]);
        c0 = f0 * c0 + i0 * q0;
        c1 = f1 * c1 + i1 * q1;

        // LN over c (512), two values per thread
        const float muc = blk_sum(c0 + c1, sred) * (1.f / 512.f);
        const float t0 = c0 - muc, t1 = c1 - muc;
        const float varc = blk_sum(t0 * t0 + t1 * t1, sred) * (1.f / 512.f);
        const float rc = rsqrtf(varc + EPSL);
        const float h0 = o0 * tanhf(t0 * rc * lno_g[dB * 512 + tid]       + lno_b[dB * 512 + tid]);
        const float h1 = o1 * tanhf(t1 * rc * lno_g[dB * 512 + tid + 256] + lno_b[dB * 512 + tid + 256]);

        __stcg(g_h + ((size_t)dB * 64 + bB) * 512 + tid,       h0);
        __stcg(g_h + ((size_t)dB * 64 + bB) * 512 + tid + 256, h1);

        if (step == SS - 1) {
            op[(size_t)bB * 1024 + dB * 512 + tid]       = h0;
            op[(size_t)bB * 1024 + dB * 512 + tid + 256] = h1;
        }

        gbar(&nbar);   // h ready for next step's GEMM
    }
}

// ---------------- host launcher ----------------
extern "C" void kernel_launch(void* const* d_in, const int* in_sizes, int n_in,
                              void* d_out, int out_size) {
    const float* x        = (const float*)d_in[0];
    // d_in[1] = text_length (unused by the reference forward)
    const float* w_ih0    = (const float*)d_in[2];
    const float* w_hh0    = (const float*)d_in[3];
    const float* ln_ih0_g = (const float*)d_in[4];
    const float* ln_ih0_b = (const float*)d_in[5];
    const float* ln_hh0_g = (const float*)d_in[6];
    const float* ln_hh0_b = (const float*)d_in[7];
    const float* ln_ho0_g = (const float*)d_in[8];
    const float* ln_ho0_b = (const float*)d_in[9];
    const float* w_ih1    = (const float*)d_in[10];
    const float* w_hh1    = (const float*)d_in[11];
    const float* ln_ih1_g = (const float*)d_in[12];
    const float* ln_ih1_b = (const float*)d_in[13];
    const float* ln_hh1_g = (const float*)d_in[14];
    const float* ln_hh1_b = (const float*)d_in[15];
    const float* ln_ho1_g = (const float*)d_in[16];
    const float* ln_ho1_b = (const float*)d_in[17];
    float* out = (float*)d_out;

    // ---- layer 0 ----
    k_prep_wt<<<dim3(64, 16, 2), dim3(32, 8)>>>(w_hh0);
    k_init<<<256, 256>>>();
    k_gemm_ih0<<<dim3(16, 48), 256>>>(x, w_ih0);
    k_ln_rows<<<6144, 256>>>(0, ln_ih0_g, ln_ih0_b, 3072);
    k_recur<<<NBLK, 256>>>(1, ln_hh0_g, ln_hh0_b, ln_ho0_g, ln_ho0_b, nullptr);

    // ---- layer 1 ----
    k_prep_wt<<<dim3(64, 16, 2), dim3(32, 8)>>>(w_hh1);
    k_init<<<256, 256>>>();
    k_gemm_xc<<<NBLK, 256>>>(w_ih1);
    k_ln_rows<<<128, 256>>>(1, ln_ih1_g, ln_ih1_b, 64);
    k_recur<<<NBLK, 256>>>(0, ln_hh1_g, ln_hh1_b, ln_ho1_g, ln_ho1_b, out);
}

// round 12
// speedup vs baseline: 1.1746x; 1.1746x over previous
#include <cuda_runtime.h>
#include <cuda_bf16.h>
#include <cstddef>

// Problem constants
#define SS   48      // sequence length
#define NBLK 128     // persistent grid size (<= 148 SMs -> all co-resident)
#define EPSL 1e-5f

// k_recur dynamic smem layout (floats): Ah[64][516] then Wp[32][516]
#define AH_STRIDE 516
#define AH_FLOATS (64 * AH_STRIDE)                  // 33,024
#define WP_FLOATS (32 * AH_STRIDE)                  // 16,512
#define RECUR_SMEM_BYTES ((AH_FLOATS + WP_FLOATS) * 4)   // 198,144 B

// ---------------- device scratch (allocation-free rule: __device__ globals) ---
__device__ float g_g0[2 * SS * 64 * 2048];   // LN(x @ W_ih0^T): row = d*3072+s*64+b
__device__ float g_g1[2 * 64 * 2048];        // LN(xc @ W_ih1^T): row = d*64+b
__device__ float g_pre[2 * 64 * 2048];       // per-step h @ W_hh^T
__device__ float g_h[2 * 64 * 512];          // hidden state [d][b][k]
__device__ float g_xc[64 * 1024];            // concat(hf, hb) [b][1024]
__device__ unsigned g_cnt;                   // grid-barrier arrival counter

// ---------------- helpers ----------------
__device__ __forceinline__ float sigf(float x) { return 1.f / (1.f + __expf(-x)); }

// block-wide sum for 256-thread blocks (8 warps)
__device__ __forceinline__ float blk_sum8(float x, float* sred) {
#pragma unroll
    for (int o = 16; o > 0; o >>= 1) x += __shfl_down_sync(0xffffffffu, x, o);
    const int w = threadIdx.x >> 5;
    if ((threadIdx.x & 31) == 0) sred[w] = x;
    __syncthreads();
    float t = 0.f;
#pragma unroll
    for (int i = 0; i < 8; ++i) t += sred[i];
    __syncthreads();
    return t;
}

// block-wide sum for 512-thread blocks (16 warps)
__device__ __forceinline__ float blk_sum16(float x, float* sred) {
#pragma unroll
    for (int o = 16; o > 0; o >>= 1) x += __shfl_down_sync(0xffffffffu, x, o);
    const int w = threadIdx.x >> 5;
    if ((threadIdx.x & 31) == 0) sred[w] = x;
    __syncthreads();
    float t = 0.f;
#pragma unroll
    for (int i = 0; i < 16; ++i) t += sred[i];
    __syncthreads();
    return t;
}

// grid-wide barrier over exactly NBLK resident CTAs (monotonic counter).
__device__ __forceinline__ void gbar(int* nbar) {
    __syncthreads();
    if (threadIdx.x == 0) {
        ++(*nbar);
        const unsigned tgt = (unsigned)(*nbar) * NBLK;
        __threadfence();
        atomicAdd(&g_cnt, 1u);
        while (*(volatile unsigned*)&g_cnt < tgt) __nanosleep(32);
        __threadfence();
    }
    __syncthreads();
}

// ---------------- K0: init hidden state + barrier counter ----------------
__global__ void k_init() {
    const int i = blockIdx.x * 256 + threadIdx.x;
    if (i < 2 * 64 * 512) g_h[i] = 0.f;
    if (i == 0) g_cnt = 0u;
}

// ---------------- K1: input GEMM  g0raw[row][g] = x[b][s][:] . w_ih0[d][g][:]
// row = d*3072 + s*64 + b.  M=6144, N=2048, K=512. 128x128 tiles, 8x8 micro.
__global__ __launch_bounds__(256) void k_gemm_ih0(const float* __restrict__ x,
                                                  const float* __restrict__ w) {
    __shared__ float Asm[16 * 132];   // [k][m]
    __shared__ float Wsm[16 * 132];   // [k][n]
    const int tid   = threadIdx.x;
    const int tcol  = tid & 15;
    const int trow  = tid >> 4;
    const int mbase = blockIdx.y * 128;
    const int nbase = blockIdx.x * 128;
    const int d     = mbase / 3072;   // tile never straddles a direction

    float acc[8][8];
#pragma unroll
    for (int i = 0; i < 8; ++i)
#pragma unroll
        for (int j = 0; j < 8; ++j) acc[i][j] = 0.f;

    for (int k0 = 0; k0 < 512; k0 += 16) {
        __syncthreads();
#pragma unroll
        for (int it = 0; it < 2; ++it) {
            const int idx = tid + 256 * it;
            const int m   = idx >> 2;
            const int kq  = (idx & 3) * 4;
            const int rem = (mbase + m) % 3072;
            const int s   = rem >> 6;
            const int b   = rem & 63;
            float4 va = *(const float4*)(x + ((size_t)(b * 48 + s)) * 512 + k0 + kq);
            Asm[(kq + 0) * 132 + m] = va.x;
            Asm[(kq + 1) * 132 + m] = va.y;
            Asm[(kq + 2) * 132 + m] = va.z;
            Asm[(kq + 3) * 132 + m] = va.w;
            float4 vw = *(const float4*)(w + ((size_t)(d * 2048 + nbase + m)) * 512 + k0 + kq);
            Wsm[(kq + 0) * 132 + m] = vw.x;
            Wsm[(kq + 1) * 132 + m] = vw.y;
            Wsm[(kq + 2) * 132 + m] = vw.z;
            Wsm[(kq + 3) * 132 + m] = vw.w;
        }
        __syncthreads();
#pragma unroll
        for (int kk = 0; kk < 16; ++kk) {
            float4 a0 = *(const float4*)&Asm[kk * 132 + trow * 4];
            float4 a1 = *(const float4*)&Asm[kk * 132 + 64 + trow * 4];
            float4 b0 = *(const float4*)&Wsm[kk * 132 + tcol * 4];
            float4 b1 = *(const float4*)&Wsm[kk * 132 + 64 + tcol * 4];
            const float av[8] = {a0.x, a0.y, a0.z, a0.w, a1.x, a1.y, a1.z, a1.w};
            const float bv[8] = {b0.x, b0.y, b0.z, b0.w, b1.x, b1.y, b1.z, b1.w};
#pragma unroll
            for (int i = 0; i < 8; ++i)
#pragma unroll
                for (int j = 0; j < 8; ++j) acc[i][j] = fmaf(av[i], bv[j], acc[i][j]);
        }
    }
#pragma unroll
    for (int i = 0; i < 8; ++i) {
        const int m = (i < 4) ? (trow * 4 + i) : (64 + trow * 4 + (i - 4));
        const size_t ro = (size_t)(mbase + m) * 2048 + nbase;
        *(float4*)(g_g0 + ro + tcol * 4)      = make_float4(acc[i][0], acc[i][1], acc[i][2], acc[i][3]);
        *(float4*)(g_g0 + ro + 64 + tcol * 4) = make_float4(acc[i][4], acc[i][5], acc[i][6], acc[i][7]);
    }
}

// ---------------- K2: in-place row LayerNorm over width 2048 -----------------
__global__ __launch_bounds__(256) void k_ln_rows(int which,
                                                 const float* __restrict__ gam,
                                                 const float* __restrict__ bet,
                                                 int rows_per_dir) {
    __shared__ float sred[8];
    float* p = which ? g_g1 : g_g0;
    const int row = blockIdx.x;
    const int d   = row / rows_per_dir;
    const size_t base = (size_t)row * 2048;
    float v[8];
#pragma unroll
    for (int r = 0; r < 8; ++r) v[r] = p[base + threadIdx.x + 256 * r];
    float s = 0.f;
#pragma unroll
    for (int r = 0; r < 8; ++r) s += v[r];
    const float mu = blk_sum8(s, sred) * (1.f / 2048.f);
    float sq = 0.f;
#pragma unroll
    for (int r = 0; r < 8; ++r) { const float t = v[r] - mu; sq += t * t; }
    const float var = blk_sum8(sq, sred) * (1.f / 2048.f);
    const float rs  = rsqrtf(var + EPSL);
#pragma unroll
    for (int r = 0; r < 8; ++r) {
        const int idx = threadIdx.x + 256 * r;
        p[base + idx] = (v[r] - mu) * rs * gam[d * 2048 + idx] + bet[d * 2048 + idx];
    }
}

// ---------------- K3: xc GEMM  g1raw[d][b][g] = xc[b][:1024] . w_ih1[d][g][:]
__global__ __launch_bounds__(256) void k_gemm_xc(const float* __restrict__ w) {
    __shared__ float As[64 * 68];
    __shared__ float Ws[32 * 68];
    const int tid = threadIdx.x;
    const int j   = blockIdx.x;
    const int d   = j & 1;
    const int gB  = (j >> 1) * 32;
    const int tx  = tid & 31, ty = tid >> 5;
    float acc[8] = {0.f, 0.f, 0.f, 0.f, 0.f, 0.f, 0.f, 0.f};
    const float* wbase = w + ((size_t)(d * 2048 + gB)) * 1024;
    for (int k0 = 0; k0 < 1024; k0 += 64) {
        __syncthreads();
#pragma unroll
        for (int it = 0; it < 4; ++it) {
            const int idx = tid + 256 * it;
            const int b   = idx >> 4;
            const int kq  = (idx & 15) * 4;
            *(float4*)&As[b * 68 + kq] = *(const float4*)(g_xc + (size_t)b * 1024 + k0 + kq);
        }
#pragma unroll
        for (int it = 0; it < 2; ++it) {
            const int idx = tid + 256 * it;
            const int gg  = idx >> 4;
            const int kq  = (idx & 15) * 4;
            *(float4*)&Ws[gg * 68 + kq] = *(const float4*)(wbase + (size_t)gg * 1024 + k0 + kq);
        }
        __syncthreads();
#pragma unroll
        for (int kk = 0; kk < 64; kk += 4) {
            float4 wv = *(const float4*)&Ws[tx * 68 + kk];
#pragma unroll
            for (int i = 0; i < 8; ++i) {
                float4 av = *(const float4*)&As[(ty * 8 + i) * 68 + kk];
                acc[i] = fmaf(av.x, wv.x, acc[i]);
                acc[i] = fmaf(av.y, wv.y, acc[i]);
                acc[i] = fmaf(av.z, wv.z, acc[i]);
                acc[i] = fmaf(av.w, wv.w, acc[i]);
            }
        }
    }
#pragma unroll
    for (int i = 0; i < 8; ++i)
        g_g1[((size_t)d * 64 + ty * 8 + i) * 2048 + gB + tx] = acc[i];
}

// ---------------- K4: persistent recurrence kernel (512 threads) -------------
// Phase A (per CTA: dir dA, 32-g slice gB): pre = h @ W_hh^T.
//   W slice (32g x 512k, 64 KB) staged ONCE per kernel into smem (k-contiguous
//   direct copy from w_hh). h (64b x 512k, 128 KB) staged once per step.
//   Thread tile: 4 b-rows x 1 g-col. Inner loop: broadcast a-LDS.128 +
//   conflict-free w-LDS.128 (row stride 516 -> banks 4*tx+k).
// Phase B (per CTA: dir dB, batch bB): LN + gates + cell + output LN, one cell
//   element per thread.
__global__ __launch_bounds__(512, 1) void k_recur(const float* __restrict__ w_hh,
                                                  int per_step,
                                                  const float* __restrict__ lnh_g,
                                                  const float* __restrict__ lnh_b,
                                                  const float* __restrict__ lno_g,
                                                  const float* __restrict__ lno_b,
                                                  float* outp) {
    extern __shared__ float sm[];
    float* Ah = sm;               // [64][516]
    float* Wp = sm + AH_FLOATS;   // [32][516]
    __shared__ float sred[16];

    const int tid = threadIdx.x;
    const int j   = blockIdx.x;
    // phase-A identity
    const int dA = j & 1;
    const int gB = (j >> 1) * 32;
    const int tx = tid & 31;      // g col
    const int wy = tid >> 5;      // warp 0..15 -> b rows 4*wy..4*wy+3
    // phase-B identity
    const int dB = j >> 6;
    const int bB = j & 63;

    const float* gin = per_step ? g_g0 : g_g1;
    float* op = outp ? outp : g_xc;

    // ---- stage W slice once (coalesced; k contiguous in w_hh) ----
#pragma unroll
    for (int it = 0; it < 8; ++it) {
        const int idx = tid + 512 * it;       // 0..4095
        const int g   = idx >> 7;             // 0..31
        const int kq  = (idx & 127) * 4;      // 0..508
        *(float4*)&Wp[g * AH_STRIDE + kq] =
            *(const float4*)(w_hh + ((size_t)(dA * 2048 + gB + g)) * 512 + kq);
    }

    float c = 0.f;
    int nbar = 0;

    for (int step = 0; step < SS; ++step) {
        // ---- stage h once per step ----
        __syncthreads();
#pragma unroll
        for (int it = 0; it < 16; ++it) {
            const int idx = tid + 512 * it;   // 0..8191
            const int b   = idx >> 7;         // 0..63
            const int kq  = (idx & 127) * 4;
            float4 v = __ldcg((const float4*)(g_h + ((size_t)dA * 64 + b) * 512 + kq));
            *(float4*)&Ah[b * AH_STRIDE + kq] = v;
        }
        __syncthreads();

        // ---- phase A inner: 4 b-rows x 1 g, full K=512 ----
        float acc0 = 0.f, acc1 = 0.f, acc2 = 0.f, acc3 = 0.f;
        const float* arow = &Ah[(wy * 4) * AH_STRIDE];
        const float* wrow = &Wp[tx * AH_STRIDE];
#pragma unroll 8
        for (int k = 0; k < 512; k += 4) {
            float4 wv = *(const float4*)&wrow[k];
            float4 a0 = *(const float4*)&arow[k];
            float4 a1 = *(const float4*)&arow[AH_STRIDE + k];
            float4 a2 = *(const float4*)&arow[2 * AH_STRIDE + k];
            float4 a3 = *(const float4*)&arow[3 * AH_STRIDE + k];
            acc0 = fmaf(a0.x, wv.x, acc0); acc0 = fmaf(a0.y, wv.y, acc0);
            acc0 = fmaf(a0.z, wv.z, acc0); acc0 = fmaf(a0.w, wv.w, acc0);
            acc1 = fmaf(a1.x, wv.x, acc1); acc1 = fmaf(a1.y, wv.y, acc1);
            acc1 = fmaf(a1.z, wv.z, acc1); acc1 = fmaf(a1.w, wv.w, acc1);
            acc2 = fmaf(a2.x, wv.x, acc2); acc2 = fmaf(a2.y, wv.y, acc2);
            acc2 = fmaf(a2.z, wv.z, acc2); acc2 = fmaf(a2.w, wv.w, acc2);
            acc3 = fmaf(a3.x, wv.x, acc3); acc3 = fmaf(a3.y, wv.y, acc3);
            acc3 = fmaf(a3.z, wv.z, acc3); acc3 = fmaf(a3.w, wv.w, acc3);
        }
        {
            float* pr = g_pre + ((size_t)dA * 64 + wy * 4) * 2048 + gB + tx;
            __stcg(pr,            acc0);
            __stcg(pr + 2048,     acc1);
            __stcg(pr + 2 * 2048, acc2);
            __stcg(pr + 3 * 2048, acc3);
        }

        gbar(&nbar);   // pre ready

        // ---- phase B: gates, cell, output-LN for row (dB, bB) ----
        float v[4];
        const float* prow = g_pre + ((size_t)dB * 64 + bB) * 2048;
#pragma unroll
        for (int r = 0; r < 4; ++r) v[r] = __ldcg(prow + tid + 512 * r);

        float s = v[0] + v[1] + v[2] + v[3];
        const float mu = blk_sum16(s, sred) * (1.f / 2048.f);
        float sq = 0.f;
#pragma unroll
        for (int r = 0; r < 4; ++r) { const float t = v[r] - mu; sq += t * t; }
        const float var = blk_sum16(sq, sred) * (1.f / 2048.f);
        const float rs  = rsqrtf(var + EPSL);

        const int s_eff = per_step ? ((dB == 0) ? step : (SS - 1 - step)) : 0;
        const float* grow = per_step
            ? gin + (((size_t)dB * SS + s_eff) * 64 + bB) * 2048
            : gin + ((size_t)dB * 64 + bB) * 2048;

        float gate[4];
#pragma unroll
        for (int r = 0; r < 4; ++r) {
            const int idx = tid + 512 * r;
            gate[r] = grow[idx] + ((v[r] - mu) * rs * lnh_g[dB * 2048 + idx] + lnh_b[dB * 2048 + idx]);
        }
        const float ig = sigf(gate[0]);
        const float fg = sigf(gate[1]);
        const float og = sigf(gate[2]);
        const float qg = tanhf(gate[3]);
        c = fg * c + ig * qg;

        // LN over c (512 values, one per thread)
        const float muc  = blk_sum16(c, sred) * (1.f / 512.f);
        const float t0   = c - muc;
        const float varc = blk_sum16(t0 * t0, sred) * (1.f / 512.f);
        const float rc   = rsqrtf(varc + EPSL);
        const float h0   = og * tanhf(t0 * rc * lno_g[dB * 512 + tid] + lno_b[dB * 512 + tid]);

        __stcg(g_h + ((size_t)dB * 64 + bB) * 512 + tid, h0);

        if (step == SS - 1)
            op[(size_t)bB * 1024 + dB * 512 + tid] = h0;

        gbar(&nbar);   // h ready for next step's GEMM
    }
}

// ---------------- host launcher ----------------
extern "C" void kernel_launch(void* const* d_in, const int* in_sizes, int n_in,
                              void* d_out, int out_size) {
    const float* x        = (const float*)d_in[0];
    // d_in[1] = text_length (unused by the reference forward)
    const float* w_ih0    = (const float*)d_in[2];
    const float* w_hh0    = (const float*)d_in[3];
    const float* ln_ih0_g = (const float*)d_in[4];
    const float* ln_ih0_b = (const float*)d_in[5];
    const float* ln_hh0_g = (const float*)d_in[6];
    const float* ln_hh0_b = (const float*)d_in[7];
    const float* ln_ho0_g = (const float*)d_in[8];
    const float* ln_ho0_b = (const float*)d_in[9];
    const float* w_ih1    = (const float*)d_in[10];
    const float* w_hh1    = (const float*)d_in[11];
    const float* ln_ih1_g = (const float*)d_in[12];
    const float* ln_ih1_b = (const float*)d_in[13];
    const float* ln_hh1_g = (const float*)d_in[14];
    const float* ln_hh1_b = (const float*)d_in[15];
    const float* ln_ho1_g = (const float*)d_in[16];
    const float* ln_ho1_b = (const float*)d_in[17];
    float* out = (float*)d_out;

    static int smem_set = 0;
    if (!smem_set) {
        cudaFuncSetAttribute(k_recur, cudaFuncAttributeMaxDynamicSharedMemorySize,
                             RECUR_SMEM_BYTES);
        smem_set = 1;
    }

    // ---- layer 0 ----
    k_init<<<256, 256>>>();
    k_gemm_ih0<<<dim3(16, 48), 256>>>(x, w_ih0);
    k_ln_rows<<<6144, 256>>>(0, ln_ih0_g, ln_ih0_b, 3072);
    k_recur<<<NBLK, 512, RECUR_SMEM_BYTES>>>(w_hh0, 1, ln_hh0_g, ln_hh0_b,
                                             ln_ho0_g, ln_ho0_b, nullptr);

    // ---- layer 1 ----
    k_init<<<256, 256>>>();
    k_gemm_xc<<<NBLK, 256>>>(w_ih1);
    k_ln_rows<<<128, 256>>>(1, ln_ih1_g, ln_ih1_b, 64);
    k_recur<<<NBLK, 512, RECUR_SMEM_BYTES>>>(w_hh1, 0, ln_hh1_g, ln_hh1_b,
                                             ln_ho1_g, ln_ho1_b, out);
}

// round 15
// speedup vs baseline: 1.2759x; 1.0862x over previous
#include <cuda_runtime.h>
#include <cuda_bf16.h>
#include <cstddef>

// Problem constants
#define SS   48      // sequence length
#define NBLK 128     // persistent grid size (<= 148 SMs -> all co-resident)
#define EPSL 1e-5f

// k_recur dynamic smem layout (floats): Ah[64][516] then Wp[32][516]
#define AH_STRIDE 516
#define AH_FLOATS (64 * AH_STRIDE)                  // 33,024
#define WP_FLOATS (32 * AH_STRIDE)                  // 16,512
#define RECUR_SMEM_BYTES ((AH_FLOATS + WP_FLOATS) * 4)   // 198,144 B

// ---------------- device scratch (allocation-free rule: __device__ globals) ---
__device__ float g_g0[2 * SS * 64 * 2048];   // LN(x @ W_ih0^T): row = d*3072+s*64+b
__device__ float g_g1[2 * 64 * 2048];        // LN(xc @ W_ih1^T): row = d*64+b
__device__ float g_pre[2 * 64 * 2048];       // per-step h @ W_hh^T
__device__ float g_h[2 * 64 * 512];          // hidden state [d][b][k]
__device__ float g_xc[64 * 1024];            // concat(hf, hb) [b][1024]
__device__ unsigned g_cnt;                   // grid-barrier arrival counter

// ---------------- packed fp32x2 helpers ----------------
typedef unsigned long long u64t;

__device__ __forceinline__ void ffma2(u64t& d, u64t a, u64t b) {
    asm("fma.rn.f32x2 %0, %1, %2, %0;" : "+l"(d) : "l"(a), "l"(b));
}
__device__ __forceinline__ float2 unpk(u64t v) {
    float2 r; asm("mov.b64 {%0, %1}, %2;" : "=f"(r.x), "=f"(r.y) : "l"(v)); return r;
}

// ---------------- helpers ----------------
__device__ __forceinline__ float sigf(float x) { return 1.f / (1.f + __expf(-x)); }

// block-wide sum for 256-thread blocks (8 warps)
__device__ __forceinline__ float blk_sum8(float x, float* sred) {
#pragma unroll
    for (int o = 16; o > 0; o >>= 1) x += __shfl_down_sync(0xffffffffu, x, o);
    const int w = threadIdx.x >> 5;
    if ((threadIdx.x & 31) == 0) sred[w] = x;
    __syncthreads();
    float t = 0.f;
#pragma unroll
    for (int i = 0; i < 8; ++i) t += sred[i];
    __syncthreads();
    return t;
}

// block-wide sum for 512-thread blocks (16 warps)
__device__ __forceinline__ float blk_sum16(float x, float* sred) {
#pragma unroll
    for (int o = 16; o > 0; o >>= 1) x += __shfl_down_sync(0xffffffffu, x, o);
    const int w = threadIdx.x >> 5;
    if ((threadIdx.x & 31) == 0) sred[w] = x;
    __syncthreads();
    float t = 0.f;
#pragma unroll
    for (int i = 0; i < 16; ++i) t += sred[i];
    __syncthreads();
    return t;
}

// grid-wide barrier over exactly NBLK resident CTAs (monotonic counter).
__device__ __forceinline__ void gbar(int* nbar) {
    __syncthreads();
    if (threadIdx.x == 0) {
        ++(*nbar);
        const unsigned tgt = (unsigned)(*nbar) * NBLK;
        __threadfence();
        atomicAdd(&g_cnt, 1u);
        while (*(volatile unsigned*)&g_cnt < tgt) __nanosleep(32);
        __threadfence();
    }
    __syncthreads();
}

// ---------------- K0: init hidden state + barrier counter ----------------
__global__ void k_init() {
    const int i = blockIdx.x * 256 + threadIdx.x;
    if (i < 2 * 64 * 512) g_h[i] = 0.f;
    if (i == 0) g_cnt = 0u;
}

// ---------------- K1: input GEMM  g0raw[row][g] = x[b][s][:] . w_ih0[d][g][:]
// row = d*3072 + s*64 + b.  M=6144, N=2048, K=512. 128x128 tiles, 8x8 micro.
__global__ __launch_bounds__(256) void k_gemm_ih0(const float* __restrict__ x,
                                                  const float* __restrict__ w) {
    __shared__ float Asm[16 * 132];   // [k][m]
    __shared__ float Wsm[16 * 132];   // [k][n]
    const int tid   = threadIdx.x;
    const int tcol  = tid & 15;
    const int trow  = tid >> 4;
    const int mbase = blockIdx.y * 128;
    const int nbase = blockIdx.x * 128;
    const int d     = mbase / 3072;   // tile never straddles a direction

    float acc[8][8];
#pragma unroll
    for (int i = 0; i < 8; ++i)
#pragma unroll
        for (int j = 0; j < 8; ++j) acc[i][j] = 0.f;

    for (int k0 = 0; k0 < 512; k0 += 16) {
        __syncthreads();
#pragma unroll
        for (int it = 0; it < 2; ++it) {
            const int idx = tid + 256 * it;
            const int m   = idx >> 2;
            const int kq  = (idx & 3) * 4;
            const int rem = (mbase + m) % 3072;
            const int s   = rem >> 6;
            const int b   = rem & 63;
            float4 va = *(const float4*)(x + ((size_t)(b * 48 + s)) * 512 + k0 + kq);
            Asm[(kq + 0) * 132 + m] = va.x;
            Asm[(kq + 1) * 132 + m] = va.y;
            Asm[(kq + 2) * 132 + m] = va.z;
            Asm[(kq + 3) * 132 + m] = va.w;
            float4 vw = *(const float4*)(w + ((size_t)(d * 2048 + nbase + m)) * 512 + k0 + kq);
            Wsm[(kq + 0) * 132 + m] = vw.x;
            Wsm[(kq + 1) * 132 + m] = vw.y;
            Wsm[(kq + 2) * 132 + m] = vw.z;
            Wsm[(kq + 3) * 132 + m] = vw.w;
        }
        __syncthreads();
#pragma unroll
        for (int kk = 0; kk < 16; ++kk) {
            float4 a0 = *(const float4*)&Asm[kk * 132 + trow * 4];
            float4 a1 = *(const float4*)&Asm[kk * 132 + 64 + trow * 4];
            float4 b0 = *(const float4*)&Wsm[kk * 132 + tcol * 4];
            float4 b1 = *(const float4*)&Wsm[kk * 132 + 64 + tcol * 4];
            const float av[8] = {a0.x, a0.y, a0.z, a0.w, a1.x, a1.y, a1.z, a1.w};
            const float bv[8] = {b0.x, b0.y, b0.z, b0.w, b1.x, b1.y, b1.z, b1.w};
#pragma unroll
            for (int i = 0; i < 8; ++i)
#pragma unroll
                for (int j = 0; j < 8; ++j) acc[i][j] = fmaf(av[i], bv[j], acc[i][j]);
        }
    }
#pragma unroll
    for (int i = 0; i < 8; ++i) {
        const int m = (i < 4) ? (trow * 4 + i) : (64 + trow * 4 + (i - 4));
        const size_t ro = (size_t)(mbase + m) * 2048 + nbase;
        *(float4*)(g_g0 + ro + tcol * 4)      = make_float4(acc[i][0], acc[i][1], acc[i][2], acc[i][3]);
        *(float4*)(g_g0 + ro + 64 + tcol * 4) = make_float4(acc[i][4], acc[i][5], acc[i][6], acc[i][7]);
    }
}

// ---------------- K2: in-place row LayerNorm over width 2048 -----------------
__global__ __launch_bounds__(256) void k_ln_rows(int which,
                                                 const float* __restrict__ gam,
                                                 const float* __restrict__ bet,
                                                 int rows_per_dir) {
    __shared__ float sred[8];
    float* p = which ? g_g1 : g_g0;
    const int row = blockIdx.x;
    const int d   = row / rows_per_dir;
    const size_t base = (size_t)row * 2048;
    float v[8];
#pragma unroll
    for (int r = 0; r < 8; ++r) v[r] = p[base + threadIdx.x + 256 * r];
    float s = 0.f;
#pragma unroll
    for (int r = 0; r < 8; ++r) s += v[r];
    const float mu = blk_sum8(s, sred) * (1.f / 2048.f);
    float sq = 0.f;
#pragma unroll
    for (int r = 0; r < 8; ++r) { const float t = v[r] - mu; sq += t * t; }
    const float var = blk_sum8(sq, sred) * (1.f / 2048.f);
    const float rs  = rsqrtf(var + EPSL);
#pragma unroll
    for (int r = 0; r < 8; ++r) {
        const int idx = threadIdx.x + 256 * r;
        p[base + idx] = (v[r] - mu) * rs * gam[d * 2048 + idx] + bet[d * 2048 + idx];
    }
}

// ---------------- K3: xc GEMM  g1raw[d][b][g] = xc[b][:1024] . w_ih1[d][g][:]
__global__ __launch_bounds__(256) void k_gemm_xc(const float* __restrict__ w) {
    __shared__ float As[64 * 68];
    __shared__ float Ws[32 * 68];
    const int tid = threadIdx.x;
    const int j   = blockIdx.x;
    const int d   = j & 1;
    const int gB  = (j >> 1) * 32;
    const int tx  = tid & 31, ty = tid >> 5;
    float acc[8] = {0.f, 0.f, 0.f, 0.f, 0.f, 0.f, 0.f, 0.f};
    const float* wbase = w + ((size_t)(d * 2048 + gB)) * 1024;
    for (int k0 = 0; k0 < 1024; k0 += 64) {
        __syncthreads();
#pragma unroll
        for (int it = 0; it < 4; ++it) {
            const int idx = tid + 256 * it;
            const int b   = idx >> 4;
            const int kq  = (idx & 15) * 4;
            *(float4*)&As[b * 68 + kq] = *(const float4*)(g_xc + (size_t)b * 1024 + k0 + kq);
        }
#pragma unroll
        for (int it = 0; it < 2; ++it) {
            const int idx = tid + 256 * it;
            const int gg  = idx >> 4;
            const int kq  = (idx & 15) * 4;
            *(float4*)&Ws[gg * 68 + kq] = *(const float4*)(wbase + (size_t)gg * 1024 + k0 + kq);
        }
        __syncthreads();
#pragma unroll
        for (int kk = 0; kk < 64; kk += 4) {
            float4 wv = *(const float4*)&Ws[tx * 68 + kk];
#pragma unroll
            for (int i = 0; i < 8; ++i) {
                float4 av = *(const float4*)&As[(ty * 8 + i) * 68 + kk];
                acc[i] = fmaf(av.x, wv.x, acc[i]);
                acc[i] = fmaf(av.y, wv.y, acc[i]);
                acc[i] = fmaf(av.z, wv.z, acc[i]);
                acc[i] = fmaf(av.w, wv.w, acc[i]);
            }
        }
    }
#pragma unroll
    for (int i = 0; i < 8; ++i)
        g_g1[((size_t)d * 64 + ty * 8 + i) * 2048 + gB + tx] = acc[i];
}

// ---------------- K4: persistent recurrence kernel (512 threads) -------------
// Phase A (per CTA: dir dA, 32-g slice gB): pre = h @ W_hh^T.
//   W slice (32g x 512k, 64 KB) staged ONCE per kernel. h (64b x 512k, 128 KB)
//   staged once per step. Split-K(2): warps 0-7 handle k[0,256), warps 8-15
//   k[256,512); each warp owns 8 b-rows x 1 g-col with f32x2 packed FMAs
//   over k-pairs (both operands naturally contiguous). Cross-group reduction
//   through an 8 KB static smem buffer.
// Phase B (per CTA: dir dB, batch bB): LN + gates + cell + output LN.
__global__ __launch_bounds__(512, 1) void k_recur(const float* __restrict__ w_hh,
                                                  int per_step,
                                                  const float* __restrict__ lnh_g,
                                                  const float* __restrict__ lnh_b,
                                                  const float* __restrict__ lno_g,
                                                  const float* __restrict__ lno_b,
                                                  float* outp) {
    extern __shared__ float sm[];
    float* Ah = sm;               // [64][516]
    float* Wp = sm + AH_FLOATS;   // [32][516]
    __shared__ float red[64][32]; // split-K reduction buffer (bank tx: conflict-free)
    __shared__ float sred[16];

    const int tid = threadIdx.x;
    const int j   = blockIdx.x;
    // phase-A identity
    const int dA  = j & 1;
    const int gB  = (j >> 1) * 32;
    const int tx  = tid & 31;            // g col
    const int wrp = tid >> 5;            // 0..15
    const int kh  = (wrp >> 3) * 256;    // k-half offset
    const int rb  = (wrp & 7) * 8;       // 8 owned b-rows
    // phase-B identity
    const int dB = j >> 6;
    const int bB = j & 63;

    const float* gin = per_step ? g_g0 : g_g1;
    float* op = outp ? outp : g_xc;

    // ---- stage W slice once (coalesced; k contiguous in w_hh) ----
#pragma unroll
    for (int it = 0; it < 8; ++it) {
        const int idx = tid + 512 * it;       // 0..4095
        const int g   = idx >> 7;             // 0..31
        const int kq  = (idx & 127) * 4;      // 0..508
        *(float4*)&Wp[g * AH_STRIDE + kq] =
            *(const float4*)(w_hh + ((size_t)(dA * 2048 + gB + g)) * 512 + kq);
    }

    float c = 0.f;
    int nbar = 0;

    for (int step = 0; step < SS; ++step) {
        // ---- stage h once per step ----
        __syncthreads();
#pragma unroll
        for (int it = 0; it < 16; ++it) {
            const int idx = tid + 512 * it;   // 0..8191
            const int b   = idx >> 7;         // 0..63
            const int kq  = (idx & 127) * 4;
            float4 v = __ldcg((const float4*)(g_h + ((size_t)dA * 64 + b) * 512 + kq));
            *(float4*)&Ah[b * AH_STRIDE + kq] = v;
        }
        __syncthreads();

        // ---- phase A inner: 8 b-rows x 1 g, k-half [kh, kh+256) ----
        u64t acc[8] = {0ull, 0ull, 0ull, 0ull, 0ull, 0ull, 0ull, 0ull};
        const float* arow = &Ah[rb * AH_STRIDE];
        const float* wrow = &Wp[tx * AH_STRIDE];
#pragma unroll 8
        for (int k = kh; k < kh + 256; k += 4) {
            ulonglong2 wv = *(const ulonglong2*)&wrow[k];   // w[k..k+3] as 2 pairs
#pragma unroll
            for (int r = 0; r < 8; ++r) {
                ulonglong2 av = *(const ulonglong2*)&arow[r * AH_STRIDE + k];
                ffma2(acc[r], av.x, wv.x);
                ffma2(acc[r], av.y, wv.y);
            }
        }
        // collapse even/odd-k pair sums
        float part[8];
#pragma unroll
        for (int r = 0; r < 8; ++r) { const float2 u = unpk(acc[r]); part[r] = u.x + u.y; }

        // cross-group reduction (group B -> smem, group A adds + stores)
        if (wrp >= 8) {
#pragma unroll
            for (int r = 0; r < 8; ++r) red[rb + r][tx] = part[r];
        }
        __syncthreads();
        if (wrp < 8) {
            float* pr = g_pre + ((size_t)dA * 64 + rb) * 2048 + gB + tx;
#pragma unroll
            for (int r = 0; r < 8; ++r)
                __stcg(pr + (size_t)r * 2048, part[r] + red[rb + r][tx]);
        }

        gbar(&nbar);   // pre ready

        // ---- phase B: gates, cell, output-LN for row (dB, bB) ----
        float v[4];
        const float* prow = g_pre + ((size_t)dB * 64 + bB) * 2048;
#pragma unroll
        for (int r = 0; r < 4; ++r) v[r] = __ldcg(prow + tid + 512 * r);

        float s = v[0] + v[1] + v[2] + v[3];
        const float mu = blk_sum16(s, sred) * (1.f / 2048.f);
        float sq = 0.f;
#pragma unroll
        for (int r = 0; r < 4; ++r) { const float t = v[r] - mu; sq += t * t; }
        const float var = blk_sum16(sq, sred) * (1.f / 2048.f);
        const float rs  = rsqrtf(var + EPSL);

        const int s_eff = per_step ? ((dB == 0) ? step : (SS - 1 - step)) : 0;
        const float* grow = per_step
            ? gin + (((size_t)dB * SS + s_eff) * 64 + bB) * 2048
            : gin + ((size_t)dB * 64 + bB) * 2048;

        float gate[4];
#pragma unroll
        for (int r = 0; r < 4; ++r) {
            const int idx = tid + 512 * r;
            gate[r] = grow[idx] + ((v[r] - mu) * rs * lnh_g[dB * 2048 + idx] + lnh_b[dB * 2048 + idx]);
        }
        const float ig = sigf(gate[0]);
        const float fg = sigf(gate[1]);
        const float og = sigf(gate[2]);
        const float qg = tanhf(gate[3]);
        c = fg * c + ig * qg;

        // LN over c (512 values, one per thread)
        const float muc  = blk_sum16(c, sred) * (1.f / 512.f);
        const float t0   = c - muc;
        const float varc = blk_sum16(t0 * t0, sred) * (1.f / 512.f);
        const float rc   = rsqrtf(varc + EPSL);
        const float h0   = og * tanhf(t0 * rc * lno_g[dB * 512 + tid] + lno_b[dB * 512 + tid]);

        __stcg(g_h + ((size_t)dB * 64 + bB) * 512 + tid, h0);

        if (step == SS - 1)
            op[(size_t)bB * 1024 + dB * 512 + tid] = h0;

        gbar(&nbar);   // h ready for next step's GEMM
    }
}

// ---------------- host launcher ----------------
extern "C" void kernel_launch(void* const* d_in, const int* in_sizes, int n_in,
                              void* d_out, int out_size) {
    const float* x        = (const float*)d_in[0];
    // d_in[1] = text_length (unused by the reference forward)
    const float* w_ih0    = (const float*)d_in[2];
    const float* w_hh0    = (const float*)d_in[3];
    const float* ln_ih0_g = (const float*)d_in[4];
    const float* ln_ih0_b = (const float*)d_in[5];
    const float* ln_hh0_g = (const float*)d_in[6];
    const float* ln_hh0_b = (const float*)d_in[7];
    const float* ln_ho0_g = (const float*)d_in[8];
    const float* ln_ho0_b = (const float*)d_in[9];
    const float* w_ih1    = (const float*)d_in[10];
    const float* w_hh1    = (const float*)d_in[11];
    const float* ln_ih1_g = (const float*)d_in[12];
    const float* ln_ih1_b = (const float*)d_in[13];
    const float* ln_hh1_g = (const float*)d_in[14];
    const float* ln_hh1_b = (const float*)d_in[15];
    const float* ln_ho1_g = (const float*)d_in[16];
    const float* ln_ho1_b = (const float*)d_in[17];
    float* out = (float*)d_out;

    static int smem_set = 0;
    if (!smem_set) {
        cudaFuncSetAttribute(k_recur, cudaFuncAttributeMaxDynamicSharedMemorySize,
                             RECUR_SMEM_BYTES);
        smem_set = 1;
    }

    // ---- layer 0 ----
    k_init<<<256, 256>>>();
    k_gemm_ih0<<<dim3(16, 48), 256>>>(x, w_ih0);
    k_ln_rows<<<6144, 256>>>(0, ln_ih0_g, ln_ih0_b, 3072);
    k_recur<<<NBLK, 512, RECUR_SMEM_BYTES>>>(w_hh0, 1, ln_hh0_g, ln_hh0_b,
                                             ln_ho0_g, ln_ho0_b, nullptr);

    // ---- layer 1 ----
    k_init<<<256, 256>>>();
    k_gemm_xc<<<NBLK, 256>>>(w_ih1);
    k_ln_rows<<<128, 256>>>(1, ln_ih1_g, ln_ih1_b, 64);
    k_recur<<<NBLK, 512, RECUR_SMEM_BYTES>>>(w_hh1, 0, ln_hh1_g, ln_hh1_b,
                                             ln_ho1_g, ln_ho1_b, out);
}

// round 17
// speedup vs baseline: 1.5885x; 1.2450x over previous
#include <cuda_runtime.h>
#include <cuda_bf16.h>
#include <cstddef>

// Problem constants
#define SS   48      // sequence length
#define NBLK 128     // persistent grid size (<= 148 SMs -> all co-resident)
#define EPSL 1e-5f

// k_recur dynamic smem layout (all fp32):
//   Ap[64][516], Wp[32][516], red[3][64][34]
#define ARS 516
#define A_FLOATS (64 * ARS)              // 33,024
#define W_FLOATS (32 * ARS)              // 16,512
#define RED_STRIDE 34
#define RED_FLOATS (3 * 64 * RED_STRIDE) // 6,528
#define RECUR_SMEM_BYTES ((A_FLOATS + W_FLOATS + RED_FLOATS) * 4)  // 224,256

// ---------------- device scratch (allocation-free rule: __device__ globals) ---
__device__ float g_g0[2 * SS * 64 * 2048];   // LN(x @ W_ih0^T): row = d*3072+s*64+b
__device__ float g_g1[2 * 64 * 2048];        // LN(xc @ W_ih1^T): row = d*64+b
__device__ float g_pre[2 * 64 * 2048];       // per-step h @ W_hh^T
__device__ float g_h[2 * 64 * 512];          // hidden state [d][b][k] fp32
__device__ float g_xc[64 * 1024];            // concat(hf, hb) [b][1024]
__device__ unsigned g_cnt;                   // grid-barrier arrival counter

// ---------------- helpers ----------------
__device__ __forceinline__ float sigf(float x) { return 1.f / (1.f + __expf(-x)); }

// round-to-nearest tf32 (kept as fp32 bit pattern in a b32 reg)
__device__ __forceinline__ unsigned f2tf32(float x) {
    unsigned u;
    asm("cvt.rna.tf32.f32 %0, %1;" : "=r"(u) : "f"(x));
    return u;
}

// mma.sync m16n8k8 tf32 (f32 accum), D += A*B
__device__ __forceinline__ void mma1688(float* c, const unsigned* a,
                                        unsigned b0, unsigned b1) {
    asm volatile(
        "mma.sync.aligned.m16n8k8.row.col.f32.tf32.tf32.f32 "
        "{%0,%1,%2,%3}, {%4,%5,%6,%7}, {%8,%9}, {%0,%1,%2,%3};"
        : "+f"(c[0]), "+f"(c[1]), "+f"(c[2]), "+f"(c[3])
        : "r"(a[0]), "r"(a[1]), "r"(a[2]), "r"(a[3]), "r"(b0), "r"(b1));
}

// block-wide sum for 256-thread blocks (8 warps)
__device__ __forceinline__ float blk_sum8(float x, float* sred) {
#pragma unroll
    for (int o = 16; o > 0; o >>= 1) x += __shfl_down_sync(0xffffffffu, x, o);
    const int w = threadIdx.x >> 5;
    if ((threadIdx.x & 31) == 0) sred[w] = x;
    __syncthreads();
    float t = 0.f;
#pragma unroll
    for (int i = 0; i < 8; ++i) t += sred[i];
    __syncthreads();
    return t;
}

// block-wide sum for 512-thread blocks (16 warps)
__device__ __forceinline__ float blk_sum16(float x, float* sred) {
#pragma unroll
    for (int o = 16; o > 0; o >>= 1) x += __shfl_down_sync(0xffffffffu, x, o);
    const int w = threadIdx.x >> 5;
    if ((threadIdx.x & 31) == 0) sred[w] = x;
    __syncthreads();
    float t = 0.f;
#pragma unroll
    for (int i = 0; i < 16; ++i) t += sred[i];
    __syncthreads();
    return t;
}

// grid-wide barrier over exactly NBLK resident CTAs (monotonic counter).
__device__ __forceinline__ void gbar(int* nbar) {
    __syncthreads();
    if (threadIdx.x == 0) {
        ++(*nbar);
        const unsigned tgt = (unsigned)(*nbar) * NBLK;
        __threadfence();
        atomicAdd(&g_cnt, 1u);
        while (*(volatile unsigned*)&g_cnt < tgt) __nanosleep(32);
        __threadfence();
    }
    __syncthreads();
}

// ---------------- K0: init hidden state + barrier counter ----------------
__global__ void k_init() {
    const int i = blockIdx.x * 256 + threadIdx.x;
    if (i < 2 * 64 * 512) g_h[i] = 0.f;
    if (i == 0) g_cnt = 0u;
}

// ---------------- K1: input GEMM  g0raw[row][g] = x[b][s][:] . w_ih0[d][g][:]
// row = d*3072 + s*64 + b.  M=6144, N=2048, K=512. 128x128 tiles, 8x8 micro.
__global__ __launch_bounds__(256) void k_gemm_ih0(const float* __restrict__ x,
                                                  const float* __restrict__ w) {
    __shared__ float Asm[16 * 132];   // [k][m]
    __shared__ float Wsm[16 * 132];   // [k][n]
    const int tid   = threadIdx.x;
    const int tcol  = tid & 15;
    const int trow  = tid >> 4;
    const int mbase = blockIdx.y * 128;
    const int nbase = blockIdx.x * 128;
    const int d     = mbase / 3072;   // tile never straddles a direction

    float acc[8][8];
#pragma unroll
    for (int i = 0; i < 8; ++i)
#pragma unroll
        for (int j = 0; j < 8; ++j) acc[i][j] = 0.f;

    for (int k0 = 0; k0 < 512; k0 += 16) {
        __syncthreads();
#pragma unroll
        for (int it = 0; it < 2; ++it) {
            const int idx = tid + 256 * it;
            const int m   = idx >> 2;
            const int kq  = (idx & 3) * 4;
            const int rem = (mbase + m) % 3072;
            const int s   = rem >> 6;
            const int b   = rem & 63;
            float4 va = *(const float4*)(x + ((size_t)(b * 48 + s)) * 512 + k0 + kq);
            Asm[(kq + 0) * 132 + m] = va.x;
            Asm[(kq + 1) * 132 + m] = va.y;
            Asm[(kq + 2) * 132 + m] = va.z;
            Asm[(kq + 3) * 132 + m] = va.w;
            float4 vw = *(const float4*)(w + ((size_t)(d * 2048 + nbase + m)) * 512 + k0 + kq);
            Wsm[(kq + 0) * 132 + m] = vw.x;
            Wsm[(kq + 1) * 132 + m] = vw.y;
            Wsm[(kq + 2) * 132 + m] = vw.z;
            Wsm[(kq + 3) * 132 + m] = vw.w;
        }
        __syncthreads();
#pragma unroll
        for (int kk = 0; kk < 16; ++kk) {
            float4 a0 = *(const float4*)&Asm[kk * 132 + trow * 4];
            float4 a1 = *(const float4*)&Asm[kk * 132 + 64 + trow * 4];
            float4 b0 = *(const float4*)&Wsm[kk * 132 + tcol * 4];
            float4 b1 = *(const float4*)&Wsm[kk * 132 + 64 + tcol * 4];
            const float av[8] = {a0.x, a0.y, a0.z, a0.w, a1.x, a1.y, a1.z, a1.w};
            const float bv[8] = {b0.x, b0.y, b0.z, b0.w, b1.x, b1.y, b1.z, b1.w};
#pragma unroll
            for (int i = 0; i < 8; ++i)
#pragma unroll
                for (int j = 0; j < 8; ++j) acc[i][j] = fmaf(av[i], bv[j], acc[i][j]);
        }
    }
#pragma unroll
    for (int i = 0; i < 8; ++i) {
        const int m = (i < 4) ? (trow * 4 + i) : (64 + trow * 4 + (i - 4));
        const size_t ro = (size_t)(mbase + m) * 2048 + nbase;
        *(float4*)(g_g0 + ro + tcol * 4)      = make_float4(acc[i][0], acc[i][1], acc[i][2], acc[i][3]);
        *(float4*)(g_g0 + ro + 64 + tcol * 4) = make_float4(acc[i][4], acc[i][5], acc[i][6], acc[i][7]);
    }
}

// ---------------- K2: in-place row LayerNorm over width 2048 -----------------
__global__ __launch_bounds__(256) void k_ln_rows(int which,
                                                 const float* __restrict__ gam,
                                                 const float* __restrict__ bet,
                                                 int rows_per_dir) {
    __shared__ float sred[8];
    float* p = which ? g_g1 : g_g0;
    const int row = blockIdx.x;
    const int d   = row / rows_per_dir;
    const size_t base = (size_t)row * 2048;
    float v[8];
#pragma unroll
    for (int r = 0; r < 8; ++r) v[r] = p[base + threadIdx.x + 256 * r];
    float s = 0.f;
#pragma unroll
    for (int r = 0; r < 8; ++r) s += v[r];
    const float mu = blk_sum8(s, sred) * (1.f / 2048.f);
    float sq = 0.f;
#pragma unroll
    for (int r = 0; r < 8; ++r) { const float t = v[r] - mu; sq += t * t; }
    const float var = blk_sum8(sq, sred) * (1.f / 2048.f);
    const float rs  = rsqrtf(var + EPSL);
#pragma unroll
    for (int r = 0; r < 8; ++r) {
        const int idx = threadIdx.x + 256 * r;
        p[base + idx] = (v[r] - mu) * rs * gam[d * 2048 + idx] + bet[d * 2048 + idx];
    }
}

// ---------------- K3: xc GEMM  g1raw[d][b][g] = xc[b][:1024] . w_ih1[d][g][:]
__global__ __launch_bounds__(256) void k_gemm_xc(const float* __restrict__ w) {
    __shared__ float As[64 * 68];
    __shared__ float Ws[32 * 68];
    const int tid = threadIdx.x;
    const int j   = blockIdx.x;
    const int d   = j & 1;
    const int gB  = (j >> 1) * 32;
    const int tx  = tid & 31, ty = tid >> 5;
    float acc[8] = {0.f, 0.f, 0.f, 0.f, 0.f, 0.f, 0.f, 0.f};
    const float* wbase = w + ((size_t)(d * 2048 + gB)) * 1024;
    for (int k0 = 0; k0 < 1024; k0 += 64) {
        __syncthreads();
#pragma unroll
        for (int it = 0; it < 4; ++it) {
            const int idx = tid + 256 * it;
            const int b   = idx >> 4;
            const int kq  = (idx & 15) * 4;
            *(float4*)&As[b * 68 + kq] = *(const float4*)(g_xc + (size_t)b * 1024 + k0 + kq);
        }
#pragma unroll
        for (int it = 0; it < 2; ++it) {
            const int idx = tid + 256 * it;
            const int gg  = idx >> 4;
            const int kq  = (idx & 15) * 4;
            *(float4*)&Ws[gg * 68 + kq] = *(const float4*)(wbase + (size_t)gg * 1024 + k0 + kq);
        }
        __syncthreads();
#pragma unroll
        for (int kk = 0; kk < 64; kk += 4) {
            float4 wv = *(const float4*)&Ws[tx * 68 + kk];
#pragma unroll
            for (int i = 0; i < 8; ++i) {
                float4 av = *(const float4*)&As[(ty * 8 + i) * 68 + kk];
                acc[i] = fmaf(av.x, wv.x, acc[i]);
                acc[i] = fmaf(av.y, wv.y, acc[i]);
                acc[i] = fmaf(av.z, wv.z, acc[i]);
                acc[i] = fmaf(av.w, wv.w, acc[i]);
            }
        }
    }
#pragma unroll
    for (int i = 0; i < 8; ++i)
        g_g1[((size_t)d * 64 + ty * 8 + i) * 2048 + gB + tx] = acc[i];
}

// ---------------- K4: persistent recurrence kernel (512 threads) -------------
// Phase A (per CTA: dir dA, 32-g slice gB): pre = h @ W_hh^T via tf32 tensor
//   cores with register-level split precision:
//     x = hi + lo (hi = rna-tf32(x), lo exact fp32 residual, truncated by HW),
//     pre ~= h_hi*W_hi + h_hi*W_lo + h_lo*W_hi   (fp32 accumulate)
//   h and W live in smem as PLAIN fp32 (no precision loss at rest).
//   Warps = 4 m-tiles x 4 k-groups; each warp: mma.m16n8k8 over n=32, k=128.
//   Split-K reduced via smem.
// Phase B (per CTA: dir dB, batch bB): LN + gates + cell + output LN (fp32).
__global__ __launch_bounds__(512, 1) void k_recur(const float* __restrict__ w_hh,
                                                  int per_step,
                                                  const float* __restrict__ lnh_g,
                                                  const float* __restrict__ lnh_b,
                                                  const float* __restrict__ lno_g,
                                                  const float* __restrict__ lno_b,
                                                  float* outp) {
    extern __shared__ float sm[];
    float* Ap  = sm;                         // [64][516] fp32 h tile
    float* Wp  = sm + A_FLOATS;              // [32][516] fp32 W slice
    float* red = sm + A_FLOATS + W_FLOATS;   // [3][64][34]
    __shared__ float sred[16];

    const int tid  = threadIdx.x;
    const int j    = blockIdx.x;
    const int lane = tid & 31;
    const int wrp  = tid >> 5;
    // phase-A identity
    const int dA  = j & 1;
    const int gB  = (j >> 1) * 32;
    const int mi  = wrp & 3;          // m-tile (16 b-rows)
    const int ks  = wrp >> 2;         // k-group (128 k)
    const int grp = lane >> 2;
    const int tg  = lane & 3;
    const int r0  = mi * 16 + grp;    // fragment row (and r0+8)
    // phase-B identity
    const int dB = j >> 6;
    const int bB = j & 63;

    const float* gin = per_step ? g_g0 : g_g1;
    float* op = outp ? outp : g_xc;

    // ---- stage W slice once (coalesced fp32; k contiguous in w_hh) ----
#pragma unroll
    for (int it = 0; it < 8; ++it) {
        const int idx = tid + 512 * it;       // 0..4095
        const int g   = idx >> 7;             // 0..31
        const int kq  = (idx & 127) * 4;      // 0..508
        *(float4*)&Wp[g * ARS + kq] =
            *(const float4*)(w_hh + ((size_t)(dA * 2048 + gB + g)) * 512 + kq);
    }

    float c = 0.f;
    int nbar = 0;

    for (int step = 0; step < SS; ++step) {
        // ---- stage h once per step (fp32 float4) ----
        __syncthreads();
#pragma unroll
        for (int it = 0; it < 16; ++it) {
            const int idx = tid + 512 * it;   // 0..8191
            const int b   = idx >> 7;         // 0..63
            const int kq  = (idx & 127) * 4;
            float4 v = __ldcg((const float4*)(g_h + ((size_t)dA * 64 + b) * 512 + kq));
            *(float4*)&Ap[b * ARS + kq] = v;
        }
        __syncthreads();

        // ---- phase A: tf32 split-precision tensor-core k-loop ----
        float acc[4][4];
#pragma unroll
        for (int nt = 0; nt < 4; ++nt)
#pragma unroll
            for (int q = 0; q < 4; ++q) acc[nt][q] = 0.f;

        const int kbeg = ks * 128;
#pragma unroll 4
        for (int kb = kbeg; kb < kbeg + 128; kb += 8) {
            // A fragment (m16k8): rows r0, r0+8; cols kb+tg, kb+tg+4
            float af[4];
            af[0] = Ap[r0 * ARS + kb + tg];
            af[1] = Ap[(r0 + 8) * ARS + kb + tg];
            af[2] = Ap[r0 * ARS + kb + 4 + tg];
            af[3] = Ap[(r0 + 8) * ARS + kb + 4 + tg];
            unsigned ahi[4], alo[4];
#pragma unroll
            for (int r = 0; r < 4; ++r) {
                ahi[r] = f2tf32(af[r]);
                alo[r] = __float_as_uint(af[r] - __uint_as_float(ahi[r]));
            }
#pragma unroll
            for (int nt = 0; nt < 4; ++nt) {
                // B fragment (k8n8, col-major): n = nt*8+grp, k = kb+tg, kb+tg+4
                const int n = nt * 8 + grp;
                const float b0f = Wp[n * ARS + kb + tg];
                const float b1f = Wp[n * ARS + kb + 4 + tg];
                const unsigned bh0 = f2tf32(b0f);
                const unsigned bh1 = f2tf32(b1f);
                const unsigned bl0 = __float_as_uint(b0f - __uint_as_float(bh0));
                const unsigned bl1 = __float_as_uint(b1f - __uint_as_float(bh1));
                mma1688(acc[nt], ahi, bh0, bh1);   // hi*hi
                mma1688(acc[nt], ahi, bl0, bl1);   // hi*lo
                mma1688(acc[nt], alo, bh0, bh1);   // lo*hi
            }
        }

        // ---- split-K reduction ----
        __syncthreads();
        if (ks > 0) {
            float* rq = red + (size_t)(ks - 1) * 64 * RED_STRIDE;
#pragma unroll
            for (int nt = 0; nt < 4; ++nt) {
                *(float2*)&rq[r0 * RED_STRIDE + nt * 8 + 2 * tg]       = make_float2(acc[nt][0], acc[nt][1]);
                *(float2*)&rq[(r0 + 8) * RED_STRIDE + nt * 8 + 2 * tg] = make_float2(acc[nt][2], acc[nt][3]);
            }
        }
        __syncthreads();
        if (ks == 0) {
#pragma unroll
            for (int nt = 0; nt < 4; ++nt) {
                float2 s0 = make_float2(acc[nt][0], acc[nt][1]);
                float2 s1 = make_float2(acc[nt][2], acc[nt][3]);
#pragma unroll
                for (int q = 0; q < 3; ++q) {
                    const float2 p0 = *(const float2*)&red[(size_t)q * 64 * RED_STRIDE + r0 * RED_STRIDE + nt * 8 + 2 * tg];
                    const float2 p1 = *(const float2*)&red[(size_t)q * 64 * RED_STRIDE + (r0 + 8) * RED_STRIDE + nt * 8 + 2 * tg];
                    s0.x += p0.x; s0.y += p0.y;
                    s1.x += p1.x; s1.y += p1.y;
                }
                float* pr = g_pre + ((size_t)dA * 64 + r0) * 2048 + gB + nt * 8 + 2 * tg;
                __stcg((float2*)pr, s0);
                __stcg((float2*)(pr + 8 * 2048), s1);
            }
        }

        gbar(&nbar);   // pre ready

        // ---- phase B: gates, cell, output-LN for row (dB, bB) ----
        float v[4];
        const float* prow = g_pre + ((size_t)dB * 64 + bB) * 2048;
#pragma unroll
        for (int r = 0; r < 4; ++r) v[r] = __ldcg(prow + tid + 512 * r);

        float s = v[0] + v[1] + v[2] + v[3];
        const float mu = blk_sum16(s, sred) * (1.f / 2048.f);
        float sq = 0.f;
#pragma unroll
        for (int r = 0; r < 4; ++r) { const float t = v[r] - mu; sq += t * t; }
        const float var = blk_sum16(sq, sred) * (1.f / 2048.f);
        const float rs  = rsqrtf(var + EPSL);

        const int s_eff = per_step ? ((dB == 0) ? step : (SS - 1 - step)) : 0;
        const float* grow = per_step
            ? gin + (((size_t)dB * SS + s_eff) * 64 + bB) * 2048
            : gin + ((size_t)dB * 64 + bB) * 2048;

        float gate[4];
#pragma unroll
        for (int r = 0; r < 4; ++r) {
            const int idx = tid + 512 * r;
            gate[r] = grow[idx] + ((v[r] - mu) * rs * lnh_g[dB * 2048 + idx] + lnh_b[dB * 2048 + idx]);
        }
        const float ig = sigf(gate[0]);
        const float fg = sigf(gate[1]);
        const float og = sigf(gate[2]);
        const float qg = tanhf(gate[3]);
        c = fg * c + ig * qg;

        // LN over c (512 values, one per thread)
        const float muc  = blk_sum16(c, sred) * (1.f / 512.f);
        const float t0   = c - muc;
        const float varc = blk_sum16(t0 * t0, sred) * (1.f / 512.f);
        const float rc   = rsqrtf(varc + EPSL);
        const float h0   = og * tanhf(t0 * rc * lno_g[dB * 512 + tid] + lno_b[dB * 512 + tid]);

        __stcg(&g_h[((size_t)dB * 64 + bB) * 512 + tid], h0);

        if (step == SS - 1)
            op[(size_t)bB * 1024 + dB * 512 + tid] = h0;

        gbar(&nbar);   // h ready for next step's GEMM
    }
}

// ---------------- host launcher ----------------
extern "C" void kernel_launch(void* const* d_in, const int* in_sizes, int n_in,
                              void* d_out, int out_size) {
    const float* x        = (const float*)d_in[0];
    // d_in[1] = text_length (unused by the reference forward)
    const float* w_ih0    = (const float*)d_in[2];
    const float* w_hh0    = (const float*)d_in[3];
    const float* ln_ih0_g = (const float*)d_in[4];
    const float* ln_ih0_b = (const float*)d_in[5];
    const float* ln_hh0_g = (const float*)d_in[6];
    const float* ln_hh0_b = (const float*)d_in[7];
    const float* ln_ho0_g = (const float*)d_in[8];
    const float* ln_ho0_b = (const float*)d_in[9];
    const float* w_ih1    = (const float*)d_in[10];
    const float* w_hh1    = (const float*)d_in[11];
    const float* ln_ih1_g = (const float*)d_in[12];
    const float* ln_ih1_b = (const float*)d_in[13];
    const float* ln_hh1_g = (const float*)d_in[14];
    const float* ln_hh1_b = (const float*)d_in[15];
    const float* ln_ho1_g = (const float*)d_in[16];
    const float* ln_ho1_b = (const float*)d_in[17];
    float* out = (float*)d_out;

    static int smem_set = 0;
    if (!smem_set) {
        cudaFuncSetAttribute(k_recur, cudaFuncAttributeMaxDynamicSharedMemorySize,
                             RECUR_SMEM_BYTES);
        smem_set = 1;
    }

    // ---- layer 0 ----
    k_init<<<256, 256>>>();
    k_gemm_ih0<<<dim3(16, 48), 256>>>(x, w_ih0);
    k_ln_rows<<<6144, 256>>>(0, ln_ih0_g, ln_ih0_b, 3072);
    k_recur<<<NBLK, 512, RECUR_SMEM_BYTES>>>(w_hh0, 1, ln_hh0_g, ln_hh0_b,
                                             ln_ho0_g, ln_ho0_b, nullptr);

    // ---- layer 1 ----
    k_init<<<256, 256>>>();
    k_gemm_xc<<<NBLK, 256>>>(w_ih1);
    k_ln_rows<<<128, 256>>>(1, ln_ih1_g, ln_ih1_b, 64);
    k_recur<<<NBLK, 512, RECUR_SMEM_BYTES>>>(w_hh1, 0, ln_hh1_g, ln_hh1_b,
                                             ln_ho1_g, ln_ho1_b, out);
}